// round 7
// baseline (speedup 1.0000x reference)
#include <cuda_runtime.h>

// out[i] = sum_j S[i][j] * w[j]   (S: [n,n] row-major fp32, w: [n] fp32)
//
// Persistent single-wave kernel: grid = 1216 CTAs (8/SM), each CTA
// grid-strides over row PAIRS with the proven R6 inner body (2 rows per
// pass -> each w load feeds two S streams). __launch_bounds__(256, 8)
// pins 32 regs so occupancy stays ~96%. One wave = no wave-transition
// bubbles; each CTA streams ~13 contiguous 128KiB pair-blocks.
__global__ void __launch_bounds__(256, 8) rowdot2_persist_kernel(
    const float* __restrict__ S,
    const float* __restrict__ w,
    float* __restrict__ out,
    int n)
{
    const float4* __restrict__ w4 = reinterpret_cast<const float4*>(w);
    const int n4 = n >> 2;          // 4096 float4 per row
    const int npairs = n >> 1;      // 8192 row pairs

    const int lane = threadIdx.x & 31;
    const int wid  = threadIdx.x >> 5;
    __shared__ float warp_sums[2][8];

    for (int p = blockIdx.x; p < npairs; p += gridDim.x) {
        const int row0 = p * 2;
        const float4* __restrict__ s4a =
            reinterpret_cast<const float4*>(S + (size_t)row0 * n);
        const float4* __restrict__ s4b =
            reinterpret_cast<const float4*>(S + (size_t)(row0 + 1) * n);

        float accA = 0.0f, accB = 0.0f;

        for (int i = threadIdx.x; i < n4; i += 256) {
            float4 wa = w4[i];
            float4 sa = s4a[i];
            float4 sb = s4b[i];
            accA = fmaf(sa.x, wa.x, accA);
            accA = fmaf(sa.y, wa.y, accA);
            accA = fmaf(sa.z, wa.z, accA);
            accA = fmaf(sa.w, wa.w, accA);
            accB = fmaf(sb.x, wa.x, accB);
            accB = fmaf(sb.y, wa.y, accB);
            accB = fmaf(sb.z, wa.z, accB);
            accB = fmaf(sb.w, wa.w, accB);
        }

        // Warp reduce both accumulators
        #pragma unroll
        for (int off = 16; off > 0; off >>= 1) {
            accA += __shfl_down_sync(0xFFFFFFFFu, accA, off);
            accB += __shfl_down_sync(0xFFFFFFFFu, accB, off);
        }

        __syncthreads();   // guard warp_sums reuse from previous pair
        if (lane == 0) {
            warp_sums[0][wid] = accA;
            warp_sums[1][wid] = accB;
        }
        __syncthreads();

        if (wid == 0) {
            float v = (lane < 8) ? warp_sums[0][lane] : 0.0f;
            #pragma unroll
            for (int off = 4; off > 0; off >>= 1)
                v += __shfl_down_sync(0xFFFFFFFFu, v, off);
            if (lane == 0) out[row0] = v;
        } else if (wid == 1) {
            float v = (lane < 8) ? warp_sums[1][lane] : 0.0f;
            #pragma unroll
            for (int off = 4; off > 0; off >>= 1)
                v += __shfl_down_sync(0xFFFFFFFFu, v, off);
            if (lane == 0) out[row0 + 1] = v;
        }
    }
}

extern "C" void kernel_launch(void* const* d_in, const int* in_sizes, int n_in,
                              void* d_out, int out_size) {
    const float* S = (const float*)d_in[0];
    const float* w = (const float*)d_in[1];
    float* out = (float*)d_out;

    const int n = in_sizes[1];  // N = 16384

    // One wave: 8 CTAs/SM x 152 SMs (GB300). Grid-stride covers any
    // SM-count mismatch.
    rowdot2_persist_kernel<<<1216, 256>>>(S, w, out, n);
}

// round 8
// speedup vs baseline: 1.0581x; 1.0581x over previous
#include <cuda_runtime.h>

// out[i] = sum_j S[i][j] * w[j]   (S: [n,n] row-major fp32, w: [n] fp32)
//
// Final configuration (best of 7 measured variants, 151.6us @ 7.10 TB/s
// = 89.5% of HBM spec; compute floor at this rate is 151.3us):
//  - One CTA per row, 16384 CTAs: HW work-distributor dynamically
//    overlaps CTA drain/launch (persistent variants lose 10-15% to
//    per-row __syncthreads pipeline drains + static imbalance).
//  - 256 threads, float4 loads: 16 independent LDG.128/thread, regs=32,
//    8 CTAs/SM -> 96% occupancy (occupancy x MLP is what feeds DRAM).
//  - __launch_bounds__(256,8) pins the 32-reg operating point.
__global__ void __launch_bounds__(256, 8) rowdot_kernel(
    const float* __restrict__ S,
    const float* __restrict__ w,
    float* __restrict__ out,
    int n)
{
    const int row = blockIdx.x;
    const float4* __restrict__ s4 = reinterpret_cast<const float4*>(S + (size_t)row * n);
    const float4* __restrict__ w4 = reinterpret_cast<const float4*>(w);

    const int n4 = n >> 2;  // 4096 float4 per row
    float acc = 0.0f;

    for (int i = threadIdx.x; i < n4; i += 256) {
        float4 a = s4[i];
        float4 b = w4[i];
        acc = fmaf(a.x, b.x, acc);
        acc = fmaf(a.y, b.y, acc);
        acc = fmaf(a.z, b.z, acc);
        acc = fmaf(a.w, b.w, acc);
    }

    // Warp reduce
    #pragma unroll
    for (int off = 16; off > 0; off >>= 1)
        acc += __shfl_down_sync(0xFFFFFFFFu, acc, off);

    // Block reduce across 8 warps
    __shared__ float warp_sums[8];
    const int lane = threadIdx.x & 31;
    const int wid  = threadIdx.x >> 5;
    if (lane == 0) warp_sums[wid] = acc;
    __syncthreads();

    if (wid == 0) {
        float v = (lane < 8) ? warp_sums[lane] : 0.0f;
        #pragma unroll
        for (int off = 4; off > 0; off >>= 1)
            v += __shfl_down_sync(0xFFFFFFFFu, v, off);
        if (lane == 0) out[row] = v;
    }
}

extern "C" void kernel_launch(void* const* d_in, const int* in_sizes, int n_in,
                              void* d_out, int out_size) {
    const float* S = (const float*)d_in[0];
    const float* w = (const float*)d_in[1];
    float* out = (float*)d_out;

    const int n = in_sizes[1];  // N = 16384

    rowdot_kernel<<<n, 256>>>(S, w, out, n);
}

// round 9
// speedup vs baseline: 1.1027x; 1.0421x over previous
#include <cuda_runtime.h>

// out[i] = sum_j S[i][j] * w[j]
// One CTA per row. 256 threads, float4 loads, warp-shuffle reduction.
// NOTE: this is the best-measured variant (151.6us, 7.10 TB/s = 89.5% of
// HBM spec; traffic floor at that rate is 151.3us). The blockDim.x loop
// stride and bare __launch_bounds__(256) are intentional: they produce
// the ptxas unroll that front-batches LDG.128 (high MLP_p1). The literal
// stride + min-blocks variant of the same code measured 157.5us.
__global__ void __launch_bounds__(256) rowdot_kernel(
    const float* __restrict__ S,
    const float* __restrict__ w,
    float* __restrict__ out,
    int n)
{
    const int row = blockIdx.x;
    const float4* __restrict__ s4 = reinterpret_cast<const float4*>(S + (size_t)row * n);
    const float4* __restrict__ w4 = reinterpret_cast<const float4*>(w);

    const int n4 = n >> 2;  // n/4 float4 elements per row
    float acc = 0.0f;

    // Coalesced grid of float4 loads; 16 iterations/thread at n=16384, bd=256.
    for (int i = threadIdx.x; i < n4; i += blockDim.x) {
        float4 a = s4[i];
        float4 b = w4[i];
        acc = fmaf(a.x, b.x, acc);
        acc = fmaf(a.y, b.y, acc);
        acc = fmaf(a.z, b.z, acc);
        acc = fmaf(a.w, b.w, acc);
    }

    // Warp reduce
    #pragma unroll
    for (int off = 16; off > 0; off >>= 1)
        acc += __shfl_down_sync(0xFFFFFFFFu, acc, off);

    // Block reduce across 8 warps
    __shared__ float warp_sums[8];
    const int lane = threadIdx.x & 31;
    const int wid  = threadIdx.x >> 5;
    if (lane == 0) warp_sums[wid] = acc;
    __syncthreads();

    if (wid == 0) {
        float v = (lane < 8) ? warp_sums[lane] : 0.0f;
        #pragma unroll
        for (int off = 4; off > 0; off >>= 1)
            v += __shfl_down_sync(0xFFFFFFFFu, v, off);
        if (lane == 0) out[row] = v;
    }
}

extern "C" void kernel_launch(void* const* d_in, const int* in_sizes, int n_in,
                              void* d_out, int out_size) {
    const float* S = (const float*)d_in[0];
    const float* w = (const float*)d_in[1];
    float* out = (float*)d_out;

    const int n = in_sizes[1];  // weights length = N = 16384

    rowdot_kernel<<<n, 256>>>(S, w, out, n);
}

// round 10
// speedup vs baseline: 1.1109x; 1.0075x over previous
#include <cuda_runtime.h>

// out[i] = sum_j S[i][j] * w[j]
// One CTA per row. 256 threads, float4 loads, warp-shuffle reduction.
// FINAL: best-measured variant (151.1us, 7.15 TB/s = 89.4% of HBM spec;
// traffic floor at that rate is 150.2us -> within 0.3% of the memory wall).
// The blockDim.x loop stride and bare __launch_bounds__(256) are
// intentional: they produce the ptxas unroll that front-batches LDG.128
// (high MLP_p1). Measured-worse alternatives: persistence (-10%),
// v8 loads (-1.6%), __ldcs (-5%), 2-row blocking (tie), literal-stride +
// min-blocks codegen (-4%).
__global__ void __launch_bounds__(256) rowdot_kernel(
    const float* __restrict__ S,
    const float* __restrict__ w,
    float* __restrict__ out,
    int n)
{
    const int row = blockIdx.x;
    const float4* __restrict__ s4 = reinterpret_cast<const float4*>(S + (size_t)row * n);
    const float4* __restrict__ w4 = reinterpret_cast<const float4*>(w);

    const int n4 = n >> 2;  // n/4 float4 elements per row
    float acc = 0.0f;

    // Coalesced grid of float4 loads; 16 iterations/thread at n=16384, bd=256.
    for (int i = threadIdx.x; i < n4; i += blockDim.x) {
        float4 a = s4[i];
        float4 b = w4[i];
        acc = fmaf(a.x, b.x, acc);
        acc = fmaf(a.y, b.y, acc);
        acc = fmaf(a.z, b.z, acc);
        acc = fmaf(a.w, b.w, acc);
    }

    // Warp reduce
    #pragma unroll
    for (int off = 16; off > 0; off >>= 1)
        acc += __shfl_down_sync(0xFFFFFFFFu, acc, off);

    // Block reduce across 8 warps
    __shared__ float warp_sums[8];
    const int lane = threadIdx.x & 31;
    const int wid  = threadIdx.x >> 5;
    if (lane == 0) warp_sums[wid] = acc;
    __syncthreads();

    if (wid == 0) {
        float v = (lane < 8) ? warp_sums[lane] : 0.0f;
        #pragma unroll
        for (int off = 4; off > 0; off >>= 1)
            v += __shfl_down_sync(0xFFFFFFFFu, v, off);
        if (lane == 0) out[row] = v;
    }
}

extern "C" void kernel_launch(void* const* d_in, const int* in_sizes, int n_in,
                              void* d_out, int out_size) {
    const float* S = (const float*)d_in[0];
    const float* w = (const float*)d_in[1];
    float* out = (float*)d_out;

    const int n = in_sizes[1];  // weights length = N = 16384

    rowdot_kernel<<<n, 256>>>(S, w, out, n);
}